// round 11
// baseline (speedup 1.0000x reference)
#include <cuda_runtime.h>
#include <math.h>

#define S_LEN 60
#define D_IN  256
#define NHEAD 16
#define SC_STRIDE 68
#define V_FLOATS (S_LEN * D_IN)          // 15360
#define V_BYTES  (V_FLOATS * 4)          // 61440
#define BPB 4                            // batches per block

typedef unsigned long long u64;

__device__ __align__(16) float g_weff[NHEAD * D_IN];

__device__ __forceinline__ u64 fma2(u64 a, u64 b, u64 c) {
    u64 d;
    asm("fma.rn.f32x2 %0, %1, %2, %3;" : "=l"(d) : "l"(a), "l"(b), "l"(c));
    return d;
}
__device__ __forceinline__ u64 mul2(u64 a, u64 b) {
    u64 d;
    asm("mul.rn.f32x2 %0, %1, %2;" : "=l"(d) : "l"(a), "l"(b));
    return d;
}
__device__ __forceinline__ u64 add2(u64 a, u64 b) {
    u64 d;
    asm("add.rn.f32x2 %0, %1, %2;" : "=l"(d) : "l"(a), "l"(b));
    return d;
}
__device__ __forceinline__ float sum2(u64 a) {
    float lo = __uint_as_float((unsigned)(a & 0xffffffffull));
    float hi = __uint_as_float((unsigned)(a >> 32));
    return lo + hi;
}
__device__ __forceinline__ u64 pack2(float lo, float hi) {
    u64 d;
    asm("mov.b64 %0, {%1, %2};" : "=l"(d) : "f"(lo), "f"(hi));
    return d;
}

// ---------------------------------------------------------------------------
// Fold Q into Wk. (bias term c[h] is per-head constant -> softmax-invariant,
// dropped entirely.)
// ---------------------------------------------------------------------------
__global__ void precompute_weff(const float* __restrict__ Q,
                                const float* __restrict__ Wk) {
    const float inv_temp = 0.35355339059327373f;  // 1/sqrt(8)
    int i = threadIdx.x;  // 0..255
#pragma unroll
    for (int h = 0; h < NHEAD; ++h) {
        float s = 0.f;
#pragma unroll
        for (int d = 0; d < 8; ++d)
            s += Q[h * 8 + d] * Wk[(h * 8 + d) * D_IN + i];
        g_weff[h * D_IN + i] = s * inv_temp;
    }
}

// ---------------------------------------------------------------------------
// One 256-thread CTA per SM (1 CTA occupancy, 256-reg budget).
// Each block processes BPB batches with double-buffered bulk copies.
// All 16 heads' w_eff live in registers; each v row is read once in Phase B.
// ---------------------------------------------------------------------------
__global__ __launch_bounds__(256, 1)
void fused_attn_kernel(const float* __restrict__ v_g,
                       const unsigned char* __restrict__ pad_mask,
                       float* __restrict__ out_g,    // [B, 256]
                       float* __restrict__ attn_g,   // [H, B, S]
                       int B) {
    extern __shared__ float smem_f[];                 // 2 x 15360 floats
    __shared__ float sc_sm[NHEAD][SC_STRIDE];
    __shared__ u64 part2[128];
    __shared__ __align__(8) u64 mbar[2];

    const int t = threadIdx.x;
    const int wid = t >> 5;
    const int lane = t & 31;

    const int base = blockIdx.x * BPB;
    const int n = (B - base < BPB) ? (B - base) : BPB;
    if (n <= 0) return;

    const unsigned mb0 = (unsigned)__cvta_generic_to_shared(&mbar[0]);
    const unsigned mb1 = (unsigned)__cvta_generic_to_shared(&mbar[1]);
    const unsigned dst0 = (unsigned)__cvta_generic_to_shared(smem_f);
    const unsigned dst1 = (unsigned)__cvta_generic_to_shared(smem_f + V_FLOATS);

    if (t < 2)
        asm volatile("mbarrier.init.shared.b64 [%0], %1;"
                     :: "r"(t ? mb1 : mb0), "r"(1));
    __syncthreads();

    // ---- w preload: ALL 16 heads, 4 u64 per head per lane (128 regs) ----
    u64 wv[NHEAD][4];
    {
        const float4* wg4 = (const float4*)g_weff;   // 64 float4 per head row
#pragma unroll
        for (int h = 0; h < NHEAD; ++h) {
            float4 a = __ldg(wg4 + h * 64 + lane);
            float4 c = __ldg(wg4 + h * 64 + 32 + lane);
            wv[h][0] = pack2(a.x, a.y);
            wv[h][1] = pack2(a.z, a.w);
            wv[h][2] = pack2(c.x, c.y);
            wv[h][3] = pack2(c.z, c.w);
        }
    }

    // ---- stage batch 0 into buffer 0 ----
    if (t == 0) {
        asm volatile("mbarrier.arrive.expect_tx.shared.b64 _, [%0], %1;"
                     :: "r"(mb0), "r"(V_BYTES) : "memory");
        asm volatile(
            "cp.async.bulk.shared::cluster.global.mbarrier::complete_tx::bytes "
            "[%0], [%1], %2, [%3];"
            :: "r"(dst0), "l"(v_g + (size_t)base * V_FLOATS),
               "r"(V_BYTES), "r"(mb0) : "memory");
    }

    // head owned by this lane after the reduction tree (even lanes)
    const int my_h = lane >> 1;
    const bool b4 = (lane & 16) != 0;
    const bool b3 = (lane & 8) != 0;
    const bool b2 = (lane & 4) != 0;
    const bool b1 = (lane & 2) != 0;

    int par0 = 0, par1 = 0;

    for (int i = 0; i < n; ++i) {
        const int bi = i & 1;
        const int bb = base + i;
        const float* v_sm = smem_f + (size_t)bi * V_FLOATS;

        // prefetch next batch into the other buffer
        if (i + 1 < n && t == 0) {
            unsigned mbn = bi ? mb0 : mb1;
            unsigned dstn = bi ? dst0 : dst1;
            asm volatile("mbarrier.arrive.expect_tx.shared.b64 _, [%0], %1;"
                         :: "r"(mbn), "r"(V_BYTES) : "memory");
            asm volatile(
                "cp.async.bulk.shared::cluster.global.mbarrier::complete_tx::bytes "
                "[%0], [%1], %2, [%3];"
                :: "r"(dstn), "l"(v_g + (size_t)(bb + 1) * V_FLOATS),
                   "r"(V_BYTES), "r"(mbn) : "memory");
        }

        // wait for current buffer
        {
            unsigned mbc = bi ? mb1 : mb0;
            int par = bi ? par1 : par0;
            asm volatile(
                "{\n\t"
                ".reg .pred P;\n"
                "WAIT_%=:\n\t"
                "mbarrier.try_wait.parity.acquire.cta.shared::cta.b64 P, [%0], %1;\n\t"
                "@P bra DONE_%=;\n\t"
                "bra WAIT_%=;\n"
                "DONE_%=:\n\t"
                "}"
                :: "r"(mbc), "r"(par) : "memory");
            if (bi) par1 ^= 1; else par0 ^= 1;
        }

        // ---- Phase B: scores for all 16 heads; each row read by ONE warp ----
        {
            const ulonglong2* vb = (const ulonglong2*)v_sm + lane;
            for (int r = wid; r < S_LEN; r += 8) {
                const ulonglong2* vr = vb + (size_t)r * 64;
                ulonglong2 v0 = vr[0];     // floats 4l..4l+3
                ulonglong2 v1 = vr[32];    // floats 128+4l..131+4l
                float p[NHEAD];
#pragma unroll
                for (int h = 0; h < NHEAD; ++h) {
                    u64 a = mul2(v0.x, wv[h][0]);
                    a = fma2(v0.y, wv[h][1], a);
                    a = fma2(v1.x, wv[h][2], a);
                    a = fma2(v1.y, wv[h][3], a);
                    p[h] = sum2(a);
                }
                // value-halving tree: 16 -> 8 -> 4 -> 2 -> 1 values/lane
                float q[8];
#pragma unroll
                for (int j = 0; j < 8; ++j) {
                    float mine = b4 ? p[j + 8] : p[j];
                    float send = b4 ? p[j] : p[j + 8];
                    q[j] = mine + __shfl_xor_sync(0xffffffffu, send, 16);
                }
                float r4[4];
#pragma unroll
                for (int j = 0; j < 4; ++j) {
                    float mine = b3 ? q[j + 4] : q[j];
                    float send = b3 ? q[j] : q[j + 4];
                    r4[j] = mine + __shfl_xor_sync(0xffffffffu, send, 8);
                }
                float r2[2];
#pragma unroll
                for (int j = 0; j < 2; ++j) {
                    float mine = b2 ? r2[0] : r2[0];  // placeholder (set below)
                    (void)mine;
                    float mm = b2 ? r4[j + 2] : r4[j];
                    float ss = b2 ? r4[j] : r4[j + 2];
                    r2[j] = mm + __shfl_xor_sync(0xffffffffu, ss, 4);
                }
                float s;
                {
                    float mm = b1 ? r2[1] : r2[0];
                    float ss = b1 ? r2[0] : r2[1];
                    s = mm + __shfl_xor_sync(0xffffffffu, ss, 2);
                }
                s += __shfl_xor_sync(0xffffffffu, s, 1);
                if ((lane & 1) == 0) sc_sm[my_h][r] = s;
            }
        }
        __syncthreads();

        // ---- Phase C: masked softmax (2 heads per warp), write attn ----
        {
            const unsigned char* pm = pad_mask + (size_t)bb * S_LEN;
#pragma unroll
            for (int hh = 0; hh < 2; ++hh) {
                const int h = wid + hh * 8;
                float x0 = sc_sm[h][lane];
                const bool has1 = (lane + 32) < S_LEN;
                float x1 = has1 ? sc_sm[h][lane + 32] : -1e30f;
                if (pm[lane]) x0 = -1e6f;
                if (has1 && pm[lane + 32]) x1 = -1e6f;

                float m = fmaxf(x0, x1);
#pragma unroll
                for (int o = 16; o > 0; o >>= 1)
                    m = fmaxf(m, __shfl_xor_sync(0xffffffffu, m, o));

                float e0 = __expf(x0 - m);
                float e1 = has1 ? __expf(x1 - m) : 0.f;
                float ss = e0 + e1;
#pragma unroll
                for (int o = 16; o > 0; o >>= 1)
                    ss += __shfl_xor_sync(0xffffffffu, ss, o);
                float inv = 1.0f / ss;

                float a0 = e0 * inv;
                float a1 = e1 * inv;
                sc_sm[h][lane] = a0;
                if (has1) sc_sm[h][lane + 32] = a1;

                float* ag = attn_g + ((size_t)h * B + bb) * S_LEN;
                ag[lane] = a0;
                if (has1) ag[lane + 32] = a1;
            }
        }
        __syncthreads();

        // ---- Phase D: out = attn @ v_heads, f32x2 per column pair ----
        {
            const int cp = t & 127;     // column pair: cols 2cp, 2cp+1
            const int sh = t >> 7;      // s half
            const int h = cp >> 3;      // 8 col-pairs per head
            const u64* vc = (const u64*)v_sm + cp;   // row stride 128 u64
            u64 acc = 0ull;
            if (sh == 0) {
#pragma unroll 8
                for (int s = 0; s < 32; ++s) {
                    float a = sc_sm[h][s];
                    acc = fma2(vc[(size_t)s * 128], pack2(a, a), acc);
                }
            } else {
#pragma unroll 7
                for (int s = 32; s < S_LEN; ++s) {
                    float a = sc_sm[h][s];
                    acc = fma2(vc[(size_t)s * 128], pack2(a, a), acc);
                }
                part2[cp] = acc;
            }
            __syncthreads();
            if (sh == 0) {
                acc = add2(acc, part2[cp]);
                ((u64*)(out_g + (size_t)bb * D_IN))[cp] = acc;
            }
        }
        __syncthreads();   // buffer free for the prefetch issued next iter
    }
}

// ---------------------------------------------------------------------------
extern "C" void kernel_launch(void* const* d_in, const int* in_sizes, int n_in,
                              void* d_out, int out_size) {
    const float* v = (const float*)d_in[0];
    const float* Q = (const float*)d_in[1];
    const float* Wk = (const float*)d_in[2];
    const unsigned char* pm = (const unsigned char*)d_in[4];

    const int B = in_sizes[0] / V_FLOATS;

    float* out = (float*)d_out;                  // [B, 256]
    float* attn = out + (size_t)B * D_IN;        // [H, B, S]

    precompute_weff<<<1, 256>>>(Q, Wk);

    const size_t smem_bytes = 2 * (size_t)V_BYTES;   // double buffer
    cudaFuncSetAttribute(fused_attn_kernel,
                         cudaFuncAttributeMaxDynamicSharedMemorySize,
                         (int)smem_bytes);

    const int blocks = (B + BPB - 1) / BPB;
    fused_attn_kernel<<<blocks, 256, smem_bytes>>>(v, pm, out, attn, B);
}

// round 12
// speedup vs baseline: 1.1556x; 1.1556x over previous
#include <cuda_runtime.h>
#include <math.h>

#define S_LEN 60
#define D_IN  256
#define NHEAD 16
#define SC_STRIDE 68
#define V_FLOATS (S_LEN * D_IN)          // 15360
#define V_BYTES  (V_FLOATS * 4)          // 61440

typedef unsigned long long u64;

__device__ __align__(16) float g_weff[NHEAD * D_IN];

__device__ __forceinline__ u64 fma2(u64 a, u64 b, u64 c) {
    u64 d;
    asm("fma.rn.f32x2 %0, %1, %2, %3;" : "=l"(d) : "l"(a), "l"(b), "l"(c));
    return d;
}
__device__ __forceinline__ u64 mul2(u64 a, u64 b) {
    u64 d;
    asm("mul.rn.f32x2 %0, %1, %2;" : "=l"(d) : "l"(a), "l"(b));
    return d;
}
__device__ __forceinline__ u64 add2(u64 a, u64 b) {
    u64 d;
    asm("add.rn.f32x2 %0, %1, %2;" : "=l"(d) : "l"(a), "l"(b));
    return d;
}
__device__ __forceinline__ float sum2(u64 a) {
    float lo = __uint_as_float((unsigned)(a & 0xffffffffull));
    float hi = __uint_as_float((unsigned)(a >> 32));
    return lo + hi;
}
__device__ __forceinline__ u64 pack2(float lo, float hi) {
    u64 d;
    asm("mov.b64 %0, {%1, %2};" : "=l"(d) : "f"(lo), "f"(hi));
    return d;
}

// ---------------------------------------------------------------------------
// Fold Q into Wk (bias c[h] dropped: per-head constant is softmax-invariant).
// ---------------------------------------------------------------------------
__global__ void precompute_weff(const float* __restrict__ Q,
                                const float* __restrict__ Wk) {
    const float inv_temp = 0.35355339059327373f;  // 1/sqrt(8)
    int i = threadIdx.x;  // 0..255
#pragma unroll
    for (int h = 0; h < NHEAD; ++h) {
        float s = 0.f;
#pragma unroll
        for (int d = 0; d < 8; ++d)
            s += Q[h * 8 + d] * Wk[(h * 8 + d) * D_IN + i];
        g_weff[h * D_IN + i] = s * inv_temp;
    }
}

// ---------------------------------------------------------------------------
// One 256-thread CTA per batch, 2 CTAs/SM (16 warps).
// All 16 heads' w_eff (per k-half) in registers; v read ONCE per k-half.
// Warp = (kh, sg): k-half x s-group.
// ---------------------------------------------------------------------------
__global__ __launch_bounds__(256, 2)
void fused_attn_kernel(const float* __restrict__ v_g,
                       const unsigned char* __restrict__ pad_mask,
                       float* __restrict__ out_g,    // [B, 256]
                       float* __restrict__ attn_g,   // [H, B, S]
                       int B) {
    extern __shared__ float v_sm[];                   // 15360 floats
    __shared__ float sc_part[2][NHEAD][SC_STRIDE];    // k-half partial scores
    __shared__ u64 part2[128];
    __shared__ __align__(8) u64 mbar;

    const int t = threadIdx.x;
    const int b = blockIdx.x;
    const int wid = t >> 5;        // 0..7
    const int lane = t & 31;

    const unsigned mb = (unsigned)__cvta_generic_to_shared(&mbar);
    const unsigned dst = (unsigned)__cvta_generic_to_shared(v_sm);

    // ---- mbarrier init + bulk copy of v (61440 B) ----
    if (t == 0)
        asm volatile("mbarrier.init.shared.b64 [%0], %1;" :: "r"(mb), "r"(1));
    __syncthreads();
    if (t == 0) {
        asm volatile("mbarrier.arrive.expect_tx.shared.b64 _, [%0], %1;"
                     :: "r"(mb), "r"(V_BYTES) : "memory");
        asm volatile(
            "cp.async.bulk.shared::cluster.global.mbarrier::complete_tx::bytes "
            "[%0], [%1], %2, [%3];"
            :: "r"(dst), "l"(v_g + (size_t)b * V_FLOATS),
               "r"(V_BYTES), "r"(mb) : "memory");
    }

    // ---- w preload (overlaps copy): 16 heads x k-half, 2 u64/head/lane ----
    const int kh = wid & 1;        // k half
    const int sg = wid >> 1;       // s group: rows sg, sg+4, ...
    u64 wv[NHEAD][2];
    {
        const float4* wg4 = (const float4*)g_weff;   // 64 float4 per head row
#pragma unroll
        for (int h = 0; h < NHEAD; ++h) {
            float4 f = __ldg(wg4 + h * 64 + kh * 32 + lane);
            wv[h][0] = pack2(f.x, f.y);
            wv[h][1] = pack2(f.z, f.w);
        }
    }

    // lane-owned head after the value-halving tree (even lanes store)
    const bool b4 = (lane & 16) != 0;
    const bool b3 = (lane & 8) != 0;
    const bool b2 = (lane & 4) != 0;
    const bool b1 = (lane & 2) != 0;
    const int my_h = ((lane >> 4) & 1) * 8 + ((lane >> 3) & 1) * 4 +
                     ((lane >> 2) & 1) * 2 + ((lane >> 1) & 1);

    // ---- wait for v ----
    asm volatile(
        "{\n\t"
        ".reg .pred P;\n"
        "WAIT_%=:\n\t"
        "mbarrier.try_wait.parity.acquire.cta.shared::cta.b64 P, [%0], 0;\n\t"
        "@P bra DONE_%=;\n\t"
        "bra WAIT_%=;\n"
        "DONE_%=:\n\t"
        "}"
        :: "r"(mb) : "memory");

    // ---- Phase B: partial scores, all 16 heads, this warp's k-half ----
    {
        const ulonglong2* vb = (const ulonglong2*)v_sm + kh * 32 + lane;
        float* dst_sc = &sc_part[kh][my_h][0];

#pragma unroll 3
        for (int r = sg; r < S_LEN; r += 4) {   // 15 rows per warp
            ulonglong2 vv = vb[(size_t)r * 64];
            float p[NHEAD];
#pragma unroll
            for (int h = 0; h < NHEAD; ++h) {
                u64 a = mul2(vv.x, wv[h][0]);
                a = fma2(vv.y, wv[h][1], a);
                p[h] = sum2(a);
            }
            // value-halving tree: 16 -> 8 -> 4 -> 2 -> 1 values per lane
            float q[8];
#pragma unroll
            for (int j = 0; j < 8; ++j) {
                float mine = b4 ? p[j + 8] : p[j];
                float send = b4 ? p[j] : p[j + 8];
                q[j] = mine + __shfl_xor_sync(0xffffffffu, send, 16);
            }
            float r4[4];
#pragma unroll
            for (int j = 0; j < 4; ++j) {
                float mine = b3 ? q[j + 4] : q[j];
                float send = b3 ? q[j] : q[j + 4];
                r4[j] = mine + __shfl_xor_sync(0xffffffffu, send, 8);
            }
            float r2[2];
#pragma unroll
            for (int j = 0; j < 2; ++j) {
                float mine = b2 ? r4[j + 2] : r4[j];
                float send = b2 ? r4[j] : r4[j + 2];
                r2[j] = mine + __shfl_xor_sync(0xffffffffu, send, 4);
            }
            float s;
            {
                float mine = b1 ? r2[1] : r2[0];
                float send = b1 ? r2[0] : r2[1];
                s = mine + __shfl_xor_sync(0xffffffffu, send, 2);
            }
            s += __shfl_xor_sync(0xffffffffu, s, 1);
            if ((lane & 1) == 0) dst_sc[r] = s;
        }
    }
    __syncthreads();

    // ---- Phase C: combine k-halves, masked softmax (2 heads/warp) ----
    {
        const unsigned char* pm = pad_mask + (size_t)b * S_LEN;
#pragma unroll
        for (int hh = 0; hh < 2; ++hh) {
            const int h = wid + hh * 8;
            float x0 = sc_part[0][h][lane] + sc_part[1][h][lane];
            const bool has1 = (lane + 32) < S_LEN;
            float x1 = has1
                ? sc_part[0][h][lane + 32] + sc_part[1][h][lane + 32]
                : -1e30f;
            if (pm[lane]) x0 = -1e6f;
            if (has1 && pm[lane + 32]) x1 = -1e6f;

            float m = fmaxf(x0, x1);
#pragma unroll
            for (int o = 16; o > 0; o >>= 1)
                m = fmaxf(m, __shfl_xor_sync(0xffffffffu, m, o));

            float e0 = __expf(x0 - m);
            float e1 = has1 ? __expf(x1 - m) : 0.f;
            float ss = e0 + e1;
#pragma unroll
            for (int o = 16; o > 0; o >>= 1)
                ss += __shfl_xor_sync(0xffffffffu, ss, o);
            float inv = 1.0f / ss;

            float a0 = e0 * inv;
            float a1 = e1 * inv;
            sc_part[0][h][lane] = a0;
            if (has1) sc_part[0][h][lane + 32] = a1;

            float* ag = attn_g + ((size_t)h * B + b) * S_LEN;
            ag[lane] = a0;
            if (has1) ag[lane + 32] = a1;
        }
    }
    __syncthreads();

    // ---- Phase D: out = attn @ v_heads, f32x2 per column pair ----
    {
        const int cp = t & 127;     // column pair: cols 2cp, 2cp+1
        const int sh = t >> 7;      // s half
        const int h = cp >> 3;      // 8 col-pairs per head
        const u64* vc = (const u64*)v_sm + cp;   // row stride 128 u64
        u64 acc = 0ull;
        if (sh == 0) {
#pragma unroll 8
            for (int s = 0; s < 32; ++s) {
                float a = sc_part[0][h][s];
                acc = fma2(vc[(size_t)s * 128], pack2(a, a), acc);
            }
        } else {
#pragma unroll 7
            for (int s = 32; s < S_LEN; ++s) {
                float a = sc_part[0][h][s];
                acc = fma2(vc[(size_t)s * 128], pack2(a, a), acc);
            }
            part2[cp] = acc;
        }
        __syncthreads();
        if (sh == 0) {
            acc = add2(acc, part2[cp]);
            ((u64*)(out_g + (size_t)b * D_IN))[cp] = acc;
        }
    }
}

// ---------------------------------------------------------------------------
extern "C" void kernel_launch(void* const* d_in, const int* in_sizes, int n_in,
                              void* d_out, int out_size) {
    const float* v = (const float*)d_in[0];
    const float* Q = (const float*)d_in[1];
    const float* Wk = (const float*)d_in[2];
    const unsigned char* pm = (const unsigned char*)d_in[4];

    const int B = in_sizes[0] / V_FLOATS;

    float* out = (float*)d_out;                  // [B, 256]
    float* attn = out + (size_t)B * D_IN;        // [H, B, S]

    precompute_weff<<<1, 256>>>(Q, Wk);

    const size_t smem_bytes = (size_t)V_BYTES;
    cudaFuncSetAttribute(fused_attn_kernel,
                         cudaFuncAttributeMaxDynamicSharedMemorySize,
                         (int)smem_bytes);

    fused_attn_kernel<<<B, 256, smem_bytes>>>(v, pm, out, attn, B);
}

// round 13
// speedup vs baseline: 1.2717x; 1.1004x over previous
#include <cuda_runtime.h>
#include <math.h>

#define S_LEN 60
#define D_IN  256
#define NHEAD 16
#define SC_STRIDE 68
#define V_FLOATS (S_LEN * D_IN)          // 15360
#define V_BYTES  (V_FLOATS * 4)          // 61440

typedef unsigned long long u64;

__device__ __align__(16) float g_weff[NHEAD * D_IN];

__device__ __forceinline__ u64 fma2(u64 a, u64 b, u64 c) {
    u64 d;
    asm("fma.rn.f32x2 %0, %1, %2, %3;" : "=l"(d) : "l"(a), "l"(b), "l"(c));
    return d;
}
__device__ __forceinline__ u64 mul2(u64 a, u64 b) {
    u64 d;
    asm("mul.rn.f32x2 %0, %1, %2;" : "=l"(d) : "l"(a), "l"(b));
    return d;
}
__device__ __forceinline__ u64 add2(u64 a, u64 b) {
    u64 d;
    asm("add.rn.f32x2 %0, %1, %2;" : "=l"(d) : "l"(a), "l"(b));
    return d;
}
__device__ __forceinline__ float sum2(u64 a) {
    float lo = __uint_as_float((unsigned)(a & 0xffffffffull));
    float hi = __uint_as_float((unsigned)(a >> 32));
    return lo + hi;
}
__device__ __forceinline__ u64 pack2(float lo, float hi) {
    u64 d;
    asm("mov.b64 %0, {%1, %2};" : "=l"(d) : "f"(lo), "f"(hi));
    return d;
}

// ---------------------------------------------------------------------------
// Fold Q into Wk (bias c[h] dropped: per-head constant is softmax-invariant).
// ---------------------------------------------------------------------------
__global__ void precompute_weff(const float* __restrict__ Q,
                                const float* __restrict__ Wk) {
    const float inv_temp = 0.35355339059327373f;  // 1/sqrt(8)
    int i = threadIdx.x;  // 0..255
#pragma unroll
    for (int h = 0; h < NHEAD; ++h) {
        float s = 0.f;
#pragma unroll
        for (int d = 0; d < 8; ++d)
            s += Q[h * 8 + d] * Wk[(h * 8 + d) * D_IN + i];
        g_weff[h * D_IN + i] = s * inv_temp;
    }
}

// ---------------------------------------------------------------------------
// One 512-thread CTA per batch element, 2 CTAs/SM (32 warps).
// Warp = (head-quarter, s-group); sel-free reduction via permuted w-load.
// ---------------------------------------------------------------------------
__global__ __launch_bounds__(512, 2)
void fused_attn_kernel(const float* __restrict__ v_g,
                       const unsigned char* __restrict__ pad_mask,
                       float* __restrict__ out_g,    // [B, 256]
                       float* __restrict__ attn_g,   // [H, B, S]
                       int B) {
    extern __shared__ float v_sm[];                   // 15360 floats
    __shared__ float sc_sm[NHEAD][SC_STRIDE];
    __shared__ u64 part2[3][128];
    __shared__ __align__(8) u64 mbar;

    const int t = threadIdx.x;
    const int b = blockIdx.x;
    const int wid = t >> 5;        // 0..15
    const int lane = t & 31;

    const unsigned mb = (unsigned)__cvta_generic_to_shared(&mbar);
    const unsigned dst = (unsigned)__cvta_generic_to_shared(v_sm);

    // ---- mbarrier init + bulk copy of v (61440 B) ----
    if (t == 0)
        asm volatile("mbarrier.init.shared.b64 [%0], %1;" :: "r"(mb), "r"(1));
    __syncthreads();
    if (t == 0) {
        asm volatile("mbarrier.arrive.expect_tx.shared.b64 _, [%0], %1;"
                     :: "r"(mb), "r"(V_BYTES) : "memory");
        asm volatile(
            "cp.async.bulk.shared::cluster.global.mbarrier::complete_tx::bytes "
            "[%0], [%1], %2, [%3];"
            :: "r"(dst), "l"(v_g + (size_t)b * V_FLOATS),
               "r"(V_BYTES), "r"(mb) : "memory");
    }

    // ---- w preload (overlaps copy): PERMUTED order p[j] <- head hq*4+(j^e) ----
    const int hq = wid & 3;        // head quarter
    const int sq = wid >> 2;       // s group: rows sq, sq+4, ... (15 rows)
    const int e = (lane >> 3) & 3; // lane-group head offset
    u64 w0x[4], w0y[4], w1x[4], w1y[4];
    {
        const float4* wg4 = (const float4*)g_weff;   // 64 float4 per head row
#pragma unroll
        for (int j = 0; j < 4; ++j) {
            int h = hq * 4 + (j ^ e);
            float4 a = __ldg(wg4 + h * 64 + lane);        // floats 4l..4l+3
            float4 c = __ldg(wg4 + h * 64 + 32 + lane);   // floats 128+4l..
            w0x[j] = pack2(a.x, a.y);
            w0y[j] = pack2(a.z, a.w);
            w1x[j] = pack2(c.x, c.y);
            w1y[j] = pack2(c.z, c.w);
        }
    }

    // ---- wait for v ----
    asm volatile(
        "{\n\t"
        ".reg .pred P;\n"
        "WAIT_%=:\n\t"
        "mbarrier.try_wait.parity.acquire.cta.shared::cta.b64 P, [%0], 0;\n\t"
        "@P bra DONE_%=;\n\t"
        "bra WAIT_%=;\n"
        "DONE_%=:\n\t"
        "}"
        :: "r"(mb) : "memory");

    // ---- Phase B: scores; sel-free permuted tree ----
    {
        const bool store_lane = (lane & 7) == 0;
        float* dst_sc = &sc_sm[hq * 4 + e][0];
        const ulonglong2* vb = (const ulonglong2*)v_sm + lane;

#pragma unroll 5
        for (int r = sq; r < S_LEN; r += 4) {   // 15 rows per warp
            const ulonglong2* vr = vb + (size_t)r * 64;
            ulonglong2 v0 = vr[0];     // floats 4l..4l+3
            ulonglong2 v1 = vr[32];    // floats 128+4l..131+4l
            float p[4];
#pragma unroll
            for (int j = 0; j < 4; ++j) {
                u64 a = mul2(v0.x, w0x[j]);
                a = fma2(v0.y, w0y[j], a);
                a = fma2(v1.x, w1x[j], a);
                a = fma2(v1.y, w1y[j], a);
                p[j] = sum2(a);
            }
            // stage xor16 (head bit1): partner's p[j+2] is my p[j]'s head
            float q0 = p[0] + __shfl_xor_sync(0xffffffffu, p[2], 16);
            float q1 = p[1] + __shfl_xor_sync(0xffffffffu, p[3], 16);
            // stage xor8 (head bit0)
            float s = q0 + __shfl_xor_sync(0xffffffffu, q1, 8);
            // butterflies within the 8-lane group
            s += __shfl_xor_sync(0xffffffffu, s, 4);
            s += __shfl_xor_sync(0xffffffffu, s, 2);
            s += __shfl_xor_sync(0xffffffffu, s, 1);
            if (store_lane) dst_sc[r] = s;
        }
    }
    __syncthreads();

    // ---- Phase C: masked softmax over s (one head per warp), write attn ----
    {
        const unsigned char* pm = pad_mask + (size_t)b * S_LEN;
        const int h = wid;
        float x0 = sc_sm[h][lane];
        const bool has1 = (lane + 32) < S_LEN;
        float x1 = has1 ? sc_sm[h][lane + 32] : -1e30f;
        if (pm[lane]) x0 = -1e6f;
        if (has1 && pm[lane + 32]) x1 = -1e6f;

        float m = fmaxf(x0, x1);
#pragma unroll
        for (int o = 16; o > 0; o >>= 1)
            m = fmaxf(m, __shfl_xor_sync(0xffffffffu, m, o));

        float e0 = __expf(x0 - m);
        float e1 = has1 ? __expf(x1 - m) : 0.f;
        float ss = e0 + e1;
#pragma unroll
        for (int o = 16; o > 0; o >>= 1)
            ss += __shfl_xor_sync(0xffffffffu, ss, o);
        float inv = 1.0f / ss;

        float a0 = e0 * inv;
        float a1 = e1 * inv;
        sc_sm[h][lane] = a0;
        if (has1) sc_sm[h][lane + 32] = a1;

        float* ag = attn_g + ((size_t)h * B + b) * S_LEN;
        ag[lane] = a0;
        if (has1) ag[lane + 32] = a1;
    }
    __syncthreads();

    // ---- Phase D: out = attn @ v_heads, f32x2 per column pair, 4-way s ----
    {
        const int cp = t & 127;     // column pair: cols 2cp, 2cp+1
        const int sh = t >> 7;      // s quarter: 0..3, 15 s each
        const int h = cp >> 3;      // 8 col-pairs per head
        const u64* vc = (const u64*)v_sm + cp;   // row stride 128 u64
        u64 acc = 0ull;
        const int s0 = sh * 15;
#pragma unroll 5
        for (int s = s0; s < s0 + 15; ++s) {
            float a = sc_sm[h][s];
            acc = fma2(vc[(size_t)s * 128], pack2(a, a), acc);
        }
        if (sh != 0) part2[sh - 1][cp] = acc;
        __syncthreads();
        if (sh == 0) {
            acc = add2(acc, part2[0][cp]);
            acc = add2(acc, add2(part2[1][cp], part2[2][cp]));
            ((u64*)(out_g + (size_t)b * D_IN))[cp] = acc;
        }
    }
}

// ---------------------------------------------------------------------------
extern "C" void kernel_launch(void* const* d_in, const int* in_sizes, int n_in,
                              void* d_out, int out_size) {
    const float* v = (const float*)d_in[0];
    const float* Q = (const float*)d_in[1];
    const float* Wk = (const float*)d_in[2];
    const unsigned char* pm = (const unsigned char*)d_in[4];

    const int B = in_sizes[0] / V_FLOATS;

    float* out = (float*)d_out;                  // [B, 256]
    float* attn = out + (size_t)B * D_IN;        // [H, B, S]

    precompute_weff<<<1, 256>>>(Q, Wk);

    const size_t smem_bytes = (size_t)V_BYTES;
    cudaFuncSetAttribute(fused_attn_kernel,
                         cudaFuncAttributeMaxDynamicSharedMemorySize,
                         (int)smem_bytes);

    fused_attn_kernel<<<B, 512, smem_bytes>>>(v, pm, out, attn, B);
}